// round 9
// baseline (speedup 1.0000x reference)
#include <cuda_runtime.h>
#include <cuda_bf16.h>
#include <cuda_fp16.h>
#include <math.h>
#include <stdint.h>

#define NROWS 32768
#define HD    1024
#define THETA 2.0f

// ---------------------------------------------------------------------------
// Scratch (device globals; no allocations allowed)
// ---------------------------------------------------------------------------
__device__ __half g_xhi[(size_t)NROWS * HD];
__device__ __half g_xlo[(size_t)NROWS * HD];
__device__ __half g_hhi[(size_t)NROWS * HD];
__device__ __half g_hlo[(size_t)NROWS * HD];
__device__ __nv_bfloat16 g_zqh[(size_t)NROWS * HD];
__device__ __nv_bfloat16 g_h3b[(size_t)NROWS * HD];
__device__ __half g_w12h[2][(size_t)HD * HD];
__device__ __half g_w12l[2][(size_t)HD * HD];
__device__ __nv_bfloat16 g_w34[2][(size_t)HD * HD];
__device__ __half g_resh[(size_t)NROWS * HD];
__device__ __half g_resl[(size_t)NROWS * HD];
__device__ float  g_resz[(size_t)NROWS * HD];
__device__ int    g_list[NROWS];
__device__ int    g_count;
__device__ float  g_rowsum[HD];
__device__ float  g_rowsq[HD];

// ---------------------------------------------------------------------------
// PTX helpers
// ---------------------------------------------------------------------------
__device__ __forceinline__ uint32_t smem_to_u32(const void* p) {
    uint32_t a;
    asm("{ .reg .u64 t; cvta.to.shared.u64 t, %1; cvt.u32.u64 %0, t; }" : "=r"(a) : "l"(p));
    return a;
}
#define CP_ASYNC16(dst, src) \
    asm volatile("cp.async.cg.shared.global [%0], [%1], 16;" :: "r"(dst), "l"(src))
#define CP_COMMIT() asm volatile("cp.async.commit_group;" ::: "memory")
#define CP_WAIT2()  asm volatile("cp.async.wait_group 2;" ::: "memory")
#define CP_WAIT1()  asm volatile("cp.async.wait_group 1;" ::: "memory")
#define CP_WAIT0()  asm volatile("cp.async.wait_group 0;" ::: "memory")

#define LDSM4(r0, r1, r2, r3, addr) \
    asm volatile("ldmatrix.sync.aligned.m8n8.x4.shared.b16 {%0,%1,%2,%3}, [%4];" \
        : "=r"(r0), "=r"(r1), "=r"(r2), "=r"(r3) : "r"(addr))

#define MMAB(d, a, b) \
    asm volatile("mma.sync.aligned.m16n8k16.row.col.f32.bf16.bf16.f32 " \
        "{%0,%1,%2,%3}, {%4,%5,%6,%7}, {%8,%9}, {%0,%1,%2,%3};" \
        : "+f"((d)[0]), "+f"((d)[1]), "+f"((d)[2]), "+f"((d)[3]) \
        : "r"((a)[0]), "r"((a)[1]), "r"((a)[2]), "r"((a)[3]), "r"((b)[0]), "r"((b)[1]))

#define MMAH(d, a, b) \
    asm volatile("mma.sync.aligned.m16n8k16.row.col.f32.f16.f16.f32 " \
        "{%0,%1,%2,%3}, {%4,%5,%6,%7}, {%8,%9}, {%0,%1,%2,%3};" \
        : "+f"((d)[0]), "+f"((d)[1]), "+f"((d)[2]), "+f"((d)[3]) \
        : "r"((a)[0]), "r"((a)[1]), "r"((a)[2]), "r"((a)[3]), "r"((b)[0]), "r"((b)[1]))

__device__ __forceinline__ void split1h(float v, __half& h, __half& l) {
    h = __float2half_rn(v);
    l = __float2half_rn(v - __half2float(h));
}

// ---------------------------------------------------------------------------
// Prep kernels
// ---------------------------------------------------------------------------
__global__ void zero_cnt_kernel() { if (threadIdx.x == 0) g_count = 0; }

__global__ __launch_bounds__(256)
void split_act_h(const float4* __restrict__ x, __half2* __restrict__ hi,
                 __half2* __restrict__ lo)
{
    size_t i = (size_t)blockIdx.x * 256 + threadIdx.x;
    float4 v = x[i];
    __half h0,l0,h1,l1,h2,l2,h3,l3;
    split1h(v.x,h0,l0); split1h(v.y,h1,l1); split1h(v.z,h2,l2); split1h(v.w,h3,l3);
    __half2 a,b;
    a.x=h0; a.y=h1; b.x=h2; b.y=h3;
    hi[2*i]=a; hi[2*i+1]=b;
    a.x=l0; a.y=l1; b.x=l2; b.y=l3;
    lo[2*i]=a; lo[2*i+1]=b;
}

__global__ __launch_bounds__(1024)
void wsplit_h(const float* __restrict__ W, __half* __restrict__ hi,
              __half* __restrict__ lo)
{
    __shared__ float s[32][33];
    int n0 = blockIdx.x * 32, k0 = blockIdx.y * 32;
    s[threadIdx.y][threadIdx.x] = W[(size_t)(k0 + threadIdx.y) * HD + n0 + threadIdx.x];
    __syncthreads();
    float v = s[threadIdx.x][threadIdx.y];
    int n = n0 + threadIdx.y, k = k0 + threadIdx.x;
    __half h, l; split1h(v, h, l);
    hi[(size_t)n * HD + k] = h;
    lo[(size_t)n * HD + k] = l;
}

__global__ __launch_bounds__(1024)
void wt_b(const float* __restrict__ W, __nv_bfloat16* __restrict__ hi)
{
    __shared__ float s[32][33];
    int n0 = blockIdx.x * 32, k0 = blockIdx.y * 32;
    s[threadIdx.y][threadIdx.x] = W[(size_t)(k0 + threadIdx.y) * HD + n0 + threadIdx.x];
    __syncthreads();
    float v = s[threadIdx.x][threadIdx.y];
    int n = n0 + threadIdx.y, k = k0 + threadIdx.x;
    hi[(size_t)n * HD + k] = __float2bfloat16(v);
}

__global__ __launch_bounds__(256)
void cb_stats_kernel(const float* __restrict__ cb, float* __restrict__ rowsum,
                     float* __restrict__ rowsq)
{
    const int i = blockIdx.x, tid = threadIdx.x;
    const float* row = cb + (size_t)i * HD;
    float s = 0.f, q = 0.f;
    for (int j = tid; j < HD; j += 256) { float v = row[j]; s += v; q = fmaf(v, v, q); }
    __shared__ float ss[256], qq[256];
    ss[tid] = s; qq[tid] = q;
    __syncthreads();
    for (int off = 128; off > 0; off >>= 1) {
        if (tid < off) { ss[tid] += ss[tid+off]; qq[tid] += qq[tid+off]; }
        __syncthreads();
    }
    if (tid == 0) { rowsum[i] = ss[0]; rowsq[i] = qq[0]; }
}

// ---------------------------------------------------------------------------
// VQ with top-2 gap flagging + gather
// ---------------------------------------------------------------------------
__global__ __launch_bounds__(256)
void vq2_kernel(const float* __restrict__ ze, const float* __restrict__ cb,
                const float* __restrict__ rowsum, const float* __restrict__ rowsq,
                float* __restrict__ zq, __nv_bfloat16* __restrict__ zqh,
                int* __restrict__ list, int* __restrict__ cnt)
{
    const int n = blockIdx.x, tid = threadIdx.x;
    const float* z = ze + (size_t)n * HD;
    float b1 = INFINITY, b2 = INFINITY; int i1 = 0x7fffffff;
    #pragma unroll
    for (int j = 0; j < 4; j++) {
        int i = tid + j * 256;
        float zv = z[i];
        float d = fmaf(1024.0f * zv, zv, fmaf(-2.0f * zv, rowsum[i], rowsq[i]));
        if (d < b1 || (d == b1 && i < i1)) { b2 = b1; b1 = d; i1 = i; }
        else if (d < b2) b2 = d;
    }
    __shared__ float sb1[256], sb2[256]; __shared__ int si1[256];
    sb1[tid] = b1; sb2[tid] = b2; si1[tid] = i1;
    __syncthreads();
    for (int off = 128; off > 0; off >>= 1) {
        if (tid < off) {
            float o1 = sb1[tid+off], o2 = sb2[tid+off]; int oi = si1[tid+off];
            float m1 = sb1[tid], m2 = sb2[tid]; int mi = si1[tid];
            if (o1 < m1 || (o1 == m1 && oi < mi)) {
                sb1[tid] = o1; si1[tid] = oi; sb2[tid] = fminf(m1, o2);
            } else {
                sb2[tid] = fminf(m2, o1);
            }
        }
        __syncthreads();
    }
    const int idx = si1[0];
    if (tid == 0 && (sb2[0] - sb1[0]) < THETA) {
        int p = atomicAdd(cnt, 1);
        list[p] = n;
    }
    float4 v = reinterpret_cast<const float4*>(cb + (size_t)idx * HD)[tid];
    reinterpret_cast<float4*>(zq + (size_t)n * HD)[tid] = v;
    __nv_bfloat162 a, b;
    a.x = __float2bfloat16(v.x); a.y = __float2bfloat16(v.y);
    b.x = __float2bfloat16(v.z); b.y = __float2bfloat16(v.w);
    __nv_bfloat162* ph = reinterpret_cast<__nv_bfloat162*>(zqh + (size_t)n * HD);
    ph[2*tid] = a; ph[2*tid+1] = b;
}

// ---------------------------------------------------------------------------
// Rescue fix-up: exact argmin over recomputed z; overwrite z_e, z_q, zq-bf16
// ---------------------------------------------------------------------------
__global__ __launch_bounds__(256)
void rescue_dist(const float* __restrict__ resz, const float* __restrict__ cb,
                 const float* __restrict__ rowsum, const float* __restrict__ rowsq,
                 float* __restrict__ zq, float* __restrict__ ze,
                 __nv_bfloat16* __restrict__ zqh,
                 const int* __restrict__ list, const int* __restrict__ cntp)
{
    const int cnt = *cntp;
    const int b = blockIdx.x;
    if (b >= cnt) return;
    const int n = list[b];
    const int tid = threadIdx.x;
    const float* z = resz + (size_t)b * HD;

    float best = INFINITY; int bidx = 0x7fffffff;
    #pragma unroll
    for (int j = 0; j < 4; j++) {
        int i = tid + j * 256;
        float zv = z[i];
        float d = fmaf(1024.0f * zv, zv, fmaf(-2.0f * zv, rowsum[i], rowsq[i]));
        if (d < best || (d == best && i < bidx)) { best = d; bidx = i; }
    }
    __shared__ float sd[256]; __shared__ int si[256];
    sd[tid] = best; si[tid] = bidx;
    __syncthreads();
    for (int off = 128; off > 0; off >>= 1) {
        if (tid < off) {
            float d2 = sd[tid+off]; int i2 = si[tid+off];
            if (d2 < sd[tid] || (d2 == sd[tid] && i2 < si[tid])) { sd[tid]=d2; si[tid]=i2; }
        }
        __syncthreads();
    }
    const int idx = si[0];

    float4 zv4 = reinterpret_cast<const float4*>(z)[tid];
    reinterpret_cast<float4*>(ze + (size_t)n * HD)[tid] = zv4;
    float4 v = reinterpret_cast<const float4*>(cb + (size_t)idx * HD)[tid];
    reinterpret_cast<float4*>(zq + (size_t)n * HD)[tid] = v;
    __nv_bfloat162 a, bb;
    a.x = __float2bfloat16(v.x); a.y = __float2bfloat16(v.y);
    bb.x = __float2bfloat16(v.z); bb.y = __float2bfloat16(v.w);
    __nv_bfloat162* ph = reinterpret_cast<__nv_bfloat162*>(zqh + (size_t)n * HD);
    ph[2*tid] = a; ph[2*tid+1] = bb;
}

// ---------------------------------------------------------------------------
// Geometry: CTA 256x128, 256 threads, 8 warps (64x64), KC=64
// ---------------------------------------------------------------------------
#define BM 256
#define BN 128
#define KC 64
#define NKI (HD / KC)
#define THREADS 256

// ===== 2-term fp16 encoder: C = relu((Ahi+Alo)@Bh + bias) =====
#define E_AH 0
#define E_AL 32768
#define E_BH 65536
#define E_STG 81920
#define E_SMEM (2 * E_STG)   // 163840

__device__ __forceinline__ void load_e(
    uint32_t sdst, const __half* __restrict__ Ahi, const __half* __restrict__ Alo,
    const __half* __restrict__ Bh, int mbase, int nbase, int c, int tid)
{
    const int kel = c * KC;
    #pragma unroll
    for (int i = 0; i < 8; ++i) {
        int id = tid + i * THREADS;
        int row = id >> 3, u = id & 7;
        uint32_t so = row * 128 + ((u ^ (row & 7)) << 4);
        CP_ASYNC16(sdst + E_AH + so, (const char*)(Ahi + (size_t)(mbase + row) * HD + kel + u * 8));
        CP_ASYNC16(sdst + E_AL + so, (const char*)(Alo + (size_t)(mbase + row) * HD + kel + u * 8));
    }
    #pragma unroll
    for (int i = 0; i < 4; ++i) {
        int id = tid + i * THREADS;
        int row = id >> 3, u = id & 7;
        uint32_t so = row * 128 + ((u ^ (row & 7)) << 4);
        CP_ASYNC16(sdst + E_BH + so, (const char*)(Bh + (size_t)(nbase + row) * HD + kel + u * 8));
    }
}

// MODE: 0 = fp32 C; 1 = fp16 split Chi/Clo.
template<int MODE>
__global__ __launch_bounds__(THREADS, 1)
void gemm_h2(const __half* __restrict__ Ahi, const __half* __restrict__ Alo,
             const __half* __restrict__ Bh, const float* __restrict__ bias,
             float* __restrict__ Cf, __half* __restrict__ Chi, __half* __restrict__ Clo)
{
    extern __shared__ char smem[];
    const uint32_t sb = smem_to_u32(smem);
    const int tid = threadIdx.x, wid = tid >> 5, lane = tid & 31;
    const int wm = wid & 3, wn = wid >> 2;
    const int mbase = blockIdx.y * BM, nbase = blockIdx.x * BN;

    float acc[4][8][4];
    #pragma unroll
    for (int i = 0; i < 4; i++)
        #pragma unroll
        for (int j = 0; j < 8; j++)
            #pragma unroll
            for (int k = 0; k < 4; k++) acc[i][j][k] = 0.f;

    const int a_row_l = lane & 15, a_half = lane >> 4;
    const int b_n_l = (lane & 7) + ((lane >> 4) << 3), b_half = (lane >> 3) & 1;

    load_e(sb, Ahi, Alo, Bh, mbase, nbase, 0, tid);
    CP_COMMIT();

    for (int c = 0; c < NKI; ++c) {
        if (c + 1 < NKI) {
            load_e(sb + ((c + 1) & 1) * E_STG, Ahi, Alo, Bh, mbase, nbase, c + 1, tid);
            CP_COMMIT(); CP_WAIT1();
        } else CP_WAIT0();
        __syncthreads();

        const uint32_t st = sb + (c & 1) * E_STG;
        #pragma unroll
        for (int ks = 0; ks < 4; ++ks) {
            uint32_t ah[4][4], bh[8][2];
            #pragma unroll
            for (int i = 0; i < 4; ++i) {
                int row = wm * 64 + i * 16 + a_row_l, u = ks * 2 + a_half;
                LDSM4(ah[i][0], ah[i][1], ah[i][2], ah[i][3],
                      st + E_AH + row * 128 + ((u ^ (row & 7)) << 4));
            }
            #pragma unroll
            for (int jj = 0; jj < 4; ++jj) {
                int n = wn * 64 + jj * 16 + b_n_l, u = ks * 2 + b_half;
                LDSM4(bh[jj*2][0], bh[jj*2][1], bh[jj*2+1][0], bh[jj*2+1][1],
                      st + E_BH + n * 128 + ((u ^ (n & 7)) << 4));
            }
            #pragma unroll
            for (int i = 0; i < 4; ++i)
                #pragma unroll
                for (int j = 0; j < 8; ++j)
                    MMAH(acc[i][j], ah[i], bh[j]);
            #pragma unroll
            for (int i = 0; i < 4; ++i) {
                int row = wm * 64 + i * 16 + a_row_l, u = ks * 2 + a_half;
                LDSM4(ah[i][0], ah[i][1], ah[i][2], ah[i][3],
                      st + E_AL + row * 128 + ((u ^ (row & 7)) << 4));
            }
            #pragma unroll
            for (int i = 0; i < 4; ++i)
                #pragma unroll
                for (int j = 0; j < 8; ++j)
                    MMAH(acc[i][j], ah[i], bh[j]);
        }
        __syncthreads();
    }

    #pragma unroll
    for (int j = 0; j < 8; ++j) {
        const int col = nbase + wn * 64 + j * 8 + (lane & 3) * 2;
        const float2 bj = *reinterpret_cast<const float2*>(bias + col);
        #pragma unroll
        for (int i = 0; i < 4; ++i) {
            const int r0 = mbase + wm * 64 + i * 16 + (lane >> 2);
            const int r1 = r0 + 8;
            float v0 = fmaxf(acc[i][j][0] + bj.x, 0.f);
            float v1 = fmaxf(acc[i][j][1] + bj.y, 0.f);
            float v2 = fmaxf(acc[i][j][2] + bj.x, 0.f);
            float v3 = fmaxf(acc[i][j][3] + bj.y, 0.f);
            if (MODE == 0) {
                float2 p0 = {v0, v1}, p1 = {v2, v3};
                *reinterpret_cast<float2*>(Cf + (size_t)r0 * HD + col) = p0;
                *reinterpret_cast<float2*>(Cf + (size_t)r1 * HD + col) = p1;
            } else {
                __half h0,l0,h1,l1,h2,l2,h3,l3;
                split1h(v0,h0,l0); split1h(v1,h1,l1); split1h(v2,h2,l2); split1h(v3,h3,l3);
                __half2 hh0; hh0.x=h0; hh0.y=h1;
                __half2 ll0; ll0.x=l0; ll0.y=l1;
                __half2 hh1; hh1.x=h2; hh1.y=h3;
                __half2 ll1; ll1.x=l2; ll1.y=l3;
                *reinterpret_cast<__half2*>(Chi + (size_t)r0 * HD + col) = hh0;
                *reinterpret_cast<__half2*>(Clo + (size_t)r0 * HD + col) = ll0;
                *reinterpret_cast<__half2*>(Chi + (size_t)r1 * HD + col) = hh1;
                *reinterpret_cast<__half2*>(Clo + (size_t)r1 * HD + col) = ll1;
            }
        }
    }
}

// ===== 3-term fp16 rescue: C = relu(Ahi*Bh + Ahi*Bl + Alo*Bh + bias), gated =====
#define R_AH 0
#define R_AL 32768
#define R_BH 65536
#define R_BL 81920
#define R_STG 98304
#define R_SMEM (2 * R_STG)   // 196608

template<int IND>
__device__ __forceinline__ void load_r(
    uint32_t sdst, const __half* __restrict__ Ahi, const __half* __restrict__ Alo,
    const __half* __restrict__ Bh, const __half* __restrict__ Bl,
    int mbase, int nbase, int c, int tid, const int* __restrict__ list, int cnt)
{
    const int kel = c * KC;
    #pragma unroll
    for (int i = 0; i < 8; ++i) {
        int id = tid + i * THREADS;
        int row = id >> 3, u = id & 7;
        int srow = mbase + row;
        if (IND) srow = __ldg(list + min(srow, cnt - 1));
        uint32_t so = row * 128 + ((u ^ (row & 7)) << 4);
        CP_ASYNC16(sdst + R_AH + so, (const char*)(Ahi + (size_t)srow * HD + kel + u * 8));
        CP_ASYNC16(sdst + R_AL + so, (const char*)(Alo + (size_t)srow * HD + kel + u * 8));
    }
    #pragma unroll
    for (int i = 0; i < 4; ++i) {
        int id = tid + i * THREADS;
        int row = id >> 3, u = id & 7;
        uint32_t so = row * 128 + ((u ^ (row & 7)) << 4);
        CP_ASYNC16(sdst + R_BH + so, (const char*)(Bh + (size_t)(nbase + row) * HD + kel + u * 8));
        CP_ASYNC16(sdst + R_BL + so, (const char*)(Bl + (size_t)(nbase + row) * HD + kel + u * 8));
    }
}

// MODE: 0 = fp32 C; 1 = fp16 split Chi/Clo.
template<int MODE, int IND>
__global__ __launch_bounds__(THREADS, 1)
void gemm_h3(const __half* __restrict__ Ahi, const __half* __restrict__ Alo,
             const __half* __restrict__ Bh, const __half* __restrict__ Bl,
             const float* __restrict__ bias,
             float* __restrict__ Cf, __half* __restrict__ Chi, __half* __restrict__ Clo,
             const int* __restrict__ list, const int* __restrict__ cntp)
{
    const int cnt = __ldg(cntp);
    const int mbase = blockIdx.y * BM;
    if (mbase >= cnt) return;
    extern __shared__ char smem[];
    const uint32_t sb = smem_to_u32(smem);
    const int tid = threadIdx.x, wid = tid >> 5, lane = tid & 31;
    const int wm = wid & 3, wn = wid >> 2;
    const int nbase = blockIdx.x * BN;

    float acc[4][8][4];
    #pragma unroll
    for (int i = 0; i < 4; i++)
        #pragma unroll
        for (int j = 0; j < 8; j++)
            #pragma unroll
            for (int k = 0; k < 4; k++) acc[i][j][k] = 0.f;

    const int a_row_l = lane & 15, a_half = lane >> 4;
    const int b_n_l = (lane & 7) + ((lane >> 4) << 3), b_half = (lane >> 3) & 1;

    load_r<IND>(sb, Ahi, Alo, Bh, Bl, mbase, nbase, 0, tid, list, cnt);
    CP_COMMIT();

    for (int c = 0; c < NKI; ++c) {
        if (c + 1 < NKI) {
            load_r<IND>(sb + ((c + 1) & 1) * R_STG, Ahi, Alo, Bh, Bl,
                        mbase, nbase, c + 1, tid, list, cnt);
            CP_COMMIT(); CP_WAIT1();
        } else CP_WAIT0();
        __syncthreads();

        const uint32_t st = sb + (c & 1) * R_STG;
        #pragma unroll
        for (int ks = 0; ks < 4; ++ks) {
            uint32_t ah[4][4], bh[8][2], bl[8][2];
            #pragma unroll
            for (int i = 0; i < 4; ++i) {
                int row = wm * 64 + i * 16 + a_row_l, u = ks * 2 + a_half;
                LDSM4(ah[i][0], ah[i][1], ah[i][2], ah[i][3],
                      st + R_AH + row * 128 + ((u ^ (row & 7)) << 4));
            }
            #pragma unroll
            for (int jj = 0; jj < 4; ++jj) {
                int n = wn * 64 + jj * 16 + b_n_l, u = ks * 2 + b_half;
                LDSM4(bh[jj*2][0], bh[jj*2][1], bh[jj*2+1][0], bh[jj*2+1][1],
                      st + R_BH + n * 128 + ((u ^ (n & 7)) << 4));
                LDSM4(bl[jj*2][0], bl[jj*2][1], bl[jj*2+1][0], bl[jj*2+1][1],
                      st + R_BL + n * 128 + ((u ^ (n & 7)) << 4));
            }
            #pragma unroll
            for (int i = 0; i < 4; ++i)
                #pragma unroll
                for (int j = 0; j < 8; ++j) {
                    MMAH(acc[i][j], ah[i], bh[j]);
                    MMAH(acc[i][j], ah[i], bl[j]);
                }
            #pragma unroll
            for (int i = 0; i < 4; ++i) {
                int row = wm * 64 + i * 16 + a_row_l, u = ks * 2 + a_half;
                LDSM4(ah[i][0], ah[i][1], ah[i][2], ah[i][3],
                      st + R_AL + row * 128 + ((u ^ (row & 7)) << 4));
            }
            #pragma unroll
            for (int i = 0; i < 4; ++i)
                #pragma unroll
                for (int j = 0; j < 8; ++j)
                    MMAH(acc[i][j], ah[i], bh[j]);
        }
        __syncthreads();
    }

    #pragma unroll
    for (int j = 0; j < 8; ++j) {
        const int col = nbase + wn * 64 + j * 8 + (lane & 3) * 2;
        const float2 bj = *reinterpret_cast<const float2*>(bias + col);
        #pragma unroll
        for (int i = 0; i < 4; ++i) {
            const int r0 = mbase + wm * 64 + i * 16 + (lane >> 2);
            const int r1 = r0 + 8;
            float v0 = fmaxf(acc[i][j][0] + bj.x, 0.f);
            float v1 = fmaxf(acc[i][j][1] + bj.y, 0.f);
            float v2 = fmaxf(acc[i][j][2] + bj.x, 0.f);
            float v3 = fmaxf(acc[i][j][3] + bj.y, 0.f);
            if (MODE == 0) {
                float2 p0 = {v0, v1}, p1 = {v2, v3};
                *reinterpret_cast<float2*>(Cf + (size_t)r0 * HD + col) = p0;
                *reinterpret_cast<float2*>(Cf + (size_t)r1 * HD + col) = p1;
            } else {
                __half h0,l0,h1,l1,h2,l2,h3,l3;
                split1h(v0,h0,l0); split1h(v1,h1,l1); split1h(v2,h2,l2); split1h(v3,h3,l3);
                __half2 hh0; hh0.x=h0; hh0.y=h1;
                __half2 ll0; ll0.x=l0; ll0.y=l1;
                __half2 hh1; hh1.x=h2; hh1.y=h3;
                __half2 ll1; ll1.x=l2; ll1.y=l3;
                *reinterpret_cast<__half2*>(Chi + (size_t)r0 * HD + col) = hh0;
                *reinterpret_cast<__half2*>(Clo + (size_t)r0 * HD + col) = ll0;
                *reinterpret_cast<__half2*>(Chi + (size_t)r1 * HD + col) = hh1;
                *reinterpret_cast<__half2*>(Clo + (size_t)r1 * HD + col) = ll1;
            }
        }
    }
}

// ===== 1-term bf16 decoder (proven R5/R7 config) =====
#define D_A 0
#define D_B 32768
#define D_STG 49152
#define D_SMEM (3 * D_STG)   // 147456

__device__ __forceinline__ void load_d(
    uint32_t sdst, const __nv_bfloat16* __restrict__ A, const __nv_bfloat16* __restrict__ B,
    int mbase, int nbase, int c, int tid)
{
    const int kel = c * KC;
    #pragma unroll
    for (int i = 0; i < 8; ++i) {
        int id = tid + i * THREADS;
        int row = id >> 3, u = id & 7;
        CP_ASYNC16(sdst + D_A + row * 128 + ((u ^ (row & 7)) << 4),
                   (const char*)(A + (size_t)(mbase + row) * HD + kel + u * 8));
    }
    #pragma unroll
    for (int i = 0; i < 4; ++i) {
        int id = tid + i * THREADS;
        int row = id >> 3, u = id & 7;
        CP_ASYNC16(sdst + D_B + row * 128 + ((u ^ (row & 7)) << 4),
                   (const char*)(B + (size_t)(nbase + row) * HD + kel + u * 8));
    }
}

// EPI: 0 = relu, 1 = sigmoid.  MODE: 0 = fp32 C; 1 = bf16 Chi.
template<int EPI, int MODE>
__global__ __launch_bounds__(THREADS, 1)
void gemm_b1(const __nv_bfloat16* __restrict__ A, const __nv_bfloat16* __restrict__ B,
             const float* __restrict__ bias,
             float* __restrict__ Cf, __nv_bfloat16* __restrict__ Chi)
{
    extern __shared__ char smem[];
    const uint32_t sb = smem_to_u32(smem);
    const int tid = threadIdx.x, wid = tid >> 5, lane = tid & 31;
    const int wm = wid & 3, wn = wid >> 2;
    const int mbase = blockIdx.y * BM, nbase = blockIdx.x * BN;

    float acc[4][8][4];
    #pragma unroll
    for (int i = 0; i < 4; i++)
        #pragma unroll
        for (int j = 0; j < 8; j++)
            #pragma unroll
            for (int k = 0; k < 4; k++) acc[i][j][k] = 0.f;

    const int a_row_l = lane & 15, a_half = lane >> 4;
    const int b_n_l = (lane & 7) + ((lane >> 4) << 3), b_half = (lane >> 3) & 1;

    load_d(sb + 0 * D_STG, A, B, mbase, nbase, 0, tid);
    CP_COMMIT();
    load_d(sb + 1 * D_STG, A, B, mbase, nbase, 1, tid);
    CP_COMMIT();

    int buf = 0;
    for (int c = 0; c < NKI; ++c) {
        if (c + 2 < NKI) {
            int b2 = buf + 2; if (b2 >= 3) b2 -= 3;
            load_d(sb + b2 * D_STG, A, B, mbase, nbase, c + 2, tid);
            CP_COMMIT(); CP_WAIT2();
        } else if (c + 1 < NKI) CP_WAIT1();
        else CP_WAIT0();
        __syncthreads();

        const uint32_t st = sb + buf * D_STG;
        #pragma unroll
        for (int ks = 0; ks < 4; ++ks) {
            uint32_t ah[4][4], bh[8][2];
            #pragma unroll
            for (int i = 0; i < 4; ++i) {
                int row = wm * 64 + i * 16 + a_row_l, u = ks * 2 + a_half;
                LDSM4(ah[i][0], ah[i][1], ah[i][2], ah[i][3],
                      st + D_A + row * 128 + ((u ^ (row & 7)) << 4));
            }
            #pragma unroll
            for (int jj = 0; jj < 4; ++jj) {
                int n = wn * 64 + jj * 16 + b_n_l, u = ks * 2 + b_half;
                LDSM4(bh[jj*2][0], bh[jj*2][1], bh[jj*2+1][0], bh[jj*2+1][1],
                      st + D_B + n * 128 + ((u ^ (n & 7)) << 4));
            }
            #pragma unroll
            for (int i = 0; i < 4; ++i)
                #pragma unroll
                for (int j = 0; j < 8; ++j)
                    MMAB(acc[i][j], ah[i], bh[j]);
        }
        __syncthreads();
        buf = buf + 1; if (buf == 3) buf = 0;
    }

    #pragma unroll
    for (int j = 0; j < 8; ++j) {
        const int col = nbase + wn * 64 + j * 8 + (lane & 3) * 2;
        const float2 bj = *reinterpret_cast<const float2*>(bias + col);
        #pragma unroll
        for (int i = 0; i < 4; ++i) {
            const int r0 = mbase + wm * 64 + i * 16 + (lane >> 2);
            const int r1 = r0 + 8;
            float v0 = acc[i][j][0] + bj.x;
            float v1 = acc[i][j][1] + bj.y;
            float v2 = acc[i][j][2] + bj.x;
            float v3 = acc[i][j][3] + bj.y;
            if (EPI == 0) {
                v0 = fmaxf(v0, 0.f); v1 = fmaxf(v1, 0.f);
                v2 = fmaxf(v2, 0.f); v3 = fmaxf(v3, 0.f);
            } else {
                v0 = 1.f / (1.f + expf(-v0)); v1 = 1.f / (1.f + expf(-v1));
                v2 = 1.f / (1.f + expf(-v2)); v3 = 1.f / (1.f + expf(-v3));
            }
            if (MODE == 0) {
                float2 p0 = {v0, v1}, p1 = {v2, v3};
                *reinterpret_cast<float2*>(Cf + (size_t)r0 * HD + col) = p0;
                *reinterpret_cast<float2*>(Cf + (size_t)r1 * HD + col) = p1;
            } else {
                __nv_bfloat162 hh0, hh1;
                hh0.x = __float2bfloat16(v0); hh0.y = __float2bfloat16(v1);
                hh1.x = __float2bfloat16(v2); hh1.y = __float2bfloat16(v3);
                *reinterpret_cast<__nv_bfloat162*>(Chi + (size_t)r0 * HD + col) = hh0;
                *reinterpret_cast<__nv_bfloat162*>(Chi + (size_t)r1 * HD + col) = hh1;
            }
        }
    }
}

// ---------------------------------------------------------------------------
// Launch
// ---------------------------------------------------------------------------
extern "C" void kernel_launch(void* const* d_in, const int* in_sizes, int n_in,
                              void* d_out, int out_size)
{
    const float* x  = (const float*)d_in[0];
    const float* W1 = (const float*)d_in[1];
    const float* b1 = (const float*)d_in[2];
    const float* W2 = (const float*)d_in[3];
    const float* b2 = (const float*)d_in[4];
    const float* cb = (const float*)d_in[5];
    const float* W3 = (const float*)d_in[6];
    const float* b3 = (const float*)d_in[7];
    const float* W4 = (const float*)d_in[8];
    const float* b4 = (const float*)d_in[9];

    float* out = (float*)d_out;
    float* x_recon = out;
    float* z_e = out + (size_t)NROWS * HD;
    float* z_q = z_e + (size_t)NROWS * HD;

    __half *xhi, *xlo, *hhi, *hlo, *w12h, *w12l, *resh, *resl;
    __nv_bfloat16 *zqh, *h3b, *w34;
    float *rs, *rq, *resz;
    int *lst, *cnt;
    cudaGetSymbolAddress((void**)&xhi,  g_xhi);
    cudaGetSymbolAddress((void**)&xlo,  g_xlo);
    cudaGetSymbolAddress((void**)&hhi,  g_hhi);
    cudaGetSymbolAddress((void**)&hlo,  g_hlo);
    cudaGetSymbolAddress((void**)&zqh,  g_zqh);
    cudaGetSymbolAddress((void**)&h3b,  g_h3b);
    cudaGetSymbolAddress((void**)&w12h, g_w12h);
    cudaGetSymbolAddress((void**)&w12l, g_w12l);
    cudaGetSymbolAddress((void**)&w34,  g_w34);
    cudaGetSymbolAddress((void**)&resh, g_resh);
    cudaGetSymbolAddress((void**)&resl, g_resl);
    cudaGetSymbolAddress((void**)&resz, g_resz);
    cudaGetSymbolAddress((void**)&lst,  g_list);
    cudaGetSymbolAddress((void**)&cnt,  g_count);
    cudaGetSymbolAddress((void**)&rs,   g_rowsum);
    cudaGetSymbolAddress((void**)&rq,   g_rowsq);
    const size_t WSZ = (size_t)HD * HD;

    cudaFuncSetAttribute(gemm_h2<1>,   cudaFuncAttributeMaxDynamicSharedMemorySize, E_SMEM);
    cudaFuncSetAttribute(gemm_h2<0>,   cudaFuncAttributeMaxDynamicSharedMemorySize, E_SMEM);
    cudaFuncSetAttribute(gemm_h3<1,1>, cudaFuncAttributeMaxDynamicSharedMemorySize, R_SMEM);
    cudaFuncSetAttribute(gemm_h3<0,0>, cudaFuncAttributeMaxDynamicSharedMemorySize, R_SMEM);
    cudaFuncSetAttribute(gemm_b1<0,1>, cudaFuncAttributeMaxDynamicSharedMemorySize, D_SMEM);
    cudaFuncSetAttribute(gemm_b1<1,0>, cudaFuncAttributeMaxDynamicSharedMemorySize, D_SMEM);

    // ---- prep ----
    zero_cnt_kernel<<<1, 32>>>();
    split_act_h<<<(NROWS * HD / 4) / 256, 256>>>((const float4*)x,
        (__half2*)xhi, (__half2*)xlo);
    dim3 tb(32, 32), tg(HD / 32, HD / 32);
    wsplit_h<<<tg, tb>>>(W1, w12h + 0 * WSZ, w12l + 0 * WSZ);
    wsplit_h<<<tg, tb>>>(W2, w12h + 1 * WSZ, w12l + 1 * WSZ);
    wt_b   <<<tg, tb>>>(W3, w34 + 0 * WSZ);
    wt_b   <<<tg, tb>>>(W4, w34 + 1 * WSZ);
    cb_stats_kernel<<<HD, 256>>>(cb, rs, rq);

    dim3 gg(HD / BN, NROWS / BM);   // (8, 128)
    dim3 blk(THREADS);

    // encoder (2-term fp16)
    gemm_h2<1><<<gg, blk, E_SMEM>>>(xhi, xlo, w12h + 0*WSZ, b1, nullptr, hhi, hlo);
    gemm_h2<0><<<gg, blk, E_SMEM>>>(hhi, hlo, w12h + 1*WSZ, b2, z_e, nullptr, nullptr);

    // VQ with gap flagging
    vq2_kernel<<<NROWS, 256>>>(z_e, cb, rs, rq, z_q, zqh, lst, cnt);

    // rescue: 3-term fp16 recompute of flagged rows (count-gated grids)
    gemm_h3<1,1><<<gg, blk, R_SMEM>>>(xhi, xlo, w12h + 0*WSZ, w12l + 0*WSZ, b1,
                                      nullptr, resh, resl, lst, cnt);
    gemm_h3<0,0><<<gg, blk, R_SMEM>>>(resh, resl, w12h + 1*WSZ, w12l + 1*WSZ, b2,
                                      resz, nullptr, nullptr, lst, cnt);
    rescue_dist<<<NROWS, 256>>>(resz, cb, rs, rq, z_q, z_e, zqh, lst, cnt);

    // decoder (1-term bf16)
    gemm_b1<0,1><<<gg, blk, D_SMEM>>>(zqh, w34 + 0*WSZ, b3, nullptr, h3b);
    gemm_b1<1,0><<<gg, blk, D_SMEM>>>(h3b, w34 + 1*WSZ, b4, x_recon, nullptr);
}